// round 1
// baseline (speedup 1.0000x reference)
#include <cuda_runtime.h>
#include <cuda_bf16.h>
#include <cstdint>

// SkipGramMultiContext: B=16384, C_MAX=10, K_NEG=5, DIM=128, VOCAB=100000
// Inputs (metadata order):
//   d_in[0] target_words   int32  (B)
//   d_in[1] context_words  int32  (B, 10)
//   d_in[2] context_lens   int32  (B)
//   d_in[3] negative_words int32  (B, 5)
//   d_in[4] in_emb         f32    (VOCAB, 128)
//   d_in[5] out_emb        f32    (VOCAB, 128)
// Output: float32[2] = {positive_loss, negative_loss}

#define B_SAMPLES 16384
#define C_MAX 10
#define K_NEG 5
#define DIM 128
#define NSCORE (C_MAX + K_NEG)   // 15
#define WARPS_PER_BLOCK 8
#define THREADS (WARPS_PER_BLOCK * 32)

__device__ __forceinline__ float logsig(float x) {
    // log(sigmoid(x)) = min(x,0) - log1p(exp(-|x|)), numerically stable
    return fminf(x, 0.0f) - log1pf(__expf(-fabsf(x)));
}

__global__ void zero_out_kernel(float* out) {
    if (threadIdx.x < 2) out[threadIdx.x] = 0.0f;
}

__global__ __launch_bounds__(THREADS)
void skipgram_loss_kernel(const int* __restrict__ tw,
                          const int* __restrict__ cw,
                          const int* __restrict__ cl,
                          const int* __restrict__ nw,
                          const float* __restrict__ in_emb,
                          const float* __restrict__ out_emb,
                          float* __restrict__ out) {
    const int warp_id = (blockIdx.x * THREADS + threadIdx.x) >> 5;
    const int lane = threadIdx.x & 31;
    const int wib  = threadIdx.x >> 5;   // warp in block

    __shared__ float s_pos[WARPS_PER_BLOCK];
    __shared__ float s_neg[WARPS_PER_BLOCK];

    float pos_per = 0.0f, neg_per = 0.0f;

    if (warp_id < B_SAMPLES) {
        const int b = warp_id;

        // target row slice: lane holds 4 consecutive floats
        const int trow = __ldg(&tw[b]);
        const float4 t4 = *reinterpret_cast<const float4*>(
            in_emb + (size_t)trow * DIM + lane * 4);

        // lanes 0..9 fetch context indices, 10..14 fetch negative indices
        int idx = 0;
        if (lane < C_MAX)       idx = __ldg(&cw[b * C_MAX + lane]);
        else if (lane < NSCORE) idx = __ldg(&nw[b * K_NEG + (lane - C_MAX)]);
        const int len = __ldg(&cl[b]);

        // issue all 15 gathers up front -> high MLP
        float dots[NSCORE];
        #pragma unroll
        for (int r = 0; r < NSCORE; r++) {
            const int row = __shfl_sync(0xffffffffu, idx, r);
            const float4 v = *reinterpret_cast<const float4*>(
                out_emb + (size_t)row * DIM + lane * 4);
            dots[r] = fmaf(t4.x, v.x, fmaf(t4.y, v.y, fmaf(t4.z, v.z, t4.w * v.w)));
        }

        // butterfly-reduce each dot; deposit score r on lane r
        float myscore = 0.0f;
        #pragma unroll
        for (int r = 0; r < NSCORE; r++) {
            float d = dots[r];
            #pragma unroll
            for (int o = 16; o > 0; o >>= 1)
                d += __shfl_xor_sync(0xffffffffu, d, o);
            if (lane == r) myscore = d;
        }

        // each lane computes one log-sigmoid (parallel MUFU)
        float pv = 0.0f, nv = 0.0f;
        if (lane < C_MAX) {
            if (lane < len) pv = -logsig(myscore);
        } else if (lane < NSCORE) {
            nv = -logsig(-myscore);
        }

        // two final reductions
        #pragma unroll
        for (int o = 16; o > 0; o >>= 1) {
            pv += __shfl_xor_sync(0xffffffffu, pv, o);
            nv += __shfl_xor_sync(0xffffffffu, nv, o);
        }

        if (len > 0) {
            pos_per = pv / (float)len;
            neg_per = nv * (1.0f / (float)K_NEG);
        }
        // len == 0: both contributions are 0 (reference skips the sample)
    }

    if (lane == 0) {
        s_pos[wib] = pos_per;
        s_neg[wib] = neg_per;
    }
    __syncthreads();

    if (threadIdx.x == 0) {
        float ps = 0.0f, ns = 0.0f;
        #pragma unroll
        for (int w = 0; w < WARPS_PER_BLOCK; w++) { ps += s_pos[w]; ns += s_neg[w]; }
        const float invB = 1.0f / (float)B_SAMPLES;
        atomicAdd(&out[0], ps * invB);
        atomicAdd(&out[1], ns * invB);
    }
}

extern "C" void kernel_launch(void* const* d_in, const int* in_sizes, int n_in,
                              void* d_out, int out_size) {
    const int*   tw      = (const int*)d_in[0];
    const int*   cw      = (const int*)d_in[1];
    const int*   cl      = (const int*)d_in[2];
    const int*   nw      = (const int*)d_in[3];
    const float* in_emb  = (const float*)d_in[4];
    const float* out_emb = (const float*)d_in[5];
    float* out = (float*)d_out;

    zero_out_kernel<<<1, 32>>>(out);

    const int num_warps  = B_SAMPLES;
    const int num_blocks = (num_warps + WARPS_PER_BLOCK - 1) / WARPS_PER_BLOCK;
    skipgram_loss_kernel<<<num_blocks, THREADS>>>(tw, cw, cl, nw, in_emb, out_emb, out);
}

// round 2
// speedup vs baseline: 1.5821x; 1.5821x over previous
#include <cuda_runtime.h>
#include <cuda_bf16.h>
#include <cstdint>

// SkipGramMultiContext: B=16384, C_MAX=10, K_NEG=5, DIM=128, VOCAB=100000
// Output: float32[2] = {positive_loss, negative_loss}

#define B_SAMPLES 16384
#define C_MAX 10
#define K_NEG 5
#define DIM 128
#define NSCORE (C_MAX + K_NEG)   // 15
#define WARPS_PER_BLOCK 8
#define THREADS (WARPS_PER_BLOCK * 32)

__device__ __forceinline__ float neg_logsig(float x) {
    // -log(sigmoid(x)) = -min(x,0) + log(1 + exp(-|x|))
    // argument of log is in (1,2]: no cancellation, fast __logf is safe
    return __logf(1.0f + __expf(-fabsf(x))) - fminf(x, 0.0f);
}

__global__ void zero_out_kernel(float* out) {
    if (threadIdx.x < 2) out[threadIdx.x] = 0.0f;
}

__global__ __launch_bounds__(THREADS)
void skipgram_loss_kernel(const int* __restrict__ tw,
                          const int* __restrict__ cw,
                          const int* __restrict__ cl,
                          const int* __restrict__ nw,
                          const float* __restrict__ in_emb,
                          const float* __restrict__ out_emb,
                          float* __restrict__ out) {
    const int warp_id = (blockIdx.x * THREADS + threadIdx.x) >> 5;
    const int lane = threadIdx.x & 31;
    const int wib  = threadIdx.x >> 5;

    __shared__ float s_pos[WARPS_PER_BLOCK];
    __shared__ float s_neg[WARPS_PER_BLOCK];

    float pos_per = 0.0f, neg_per = 0.0f;

    if (warp_id < B_SAMPLES) {
        const int b = warp_id;

        // target row slice: lane holds 4 consecutive floats (LDG.128, coalesced)
        const int trow = __ldg(&tw[b]);
        const float4 t4 = *reinterpret_cast<const float4*>(
            in_emb + (size_t)trow * DIM + lane * 4);

        // lanes 0..9 hold context indices, 10..14 negatives
        int idx = 0;
        if (lane < C_MAX)       idx = __ldg(&cw[b * C_MAX + lane]);
        else if (lane < NSCORE) idx = __ldg(&nw[b * K_NEG + (lane - C_MAX)]);
        const int len = __ldg(&cl[b]);

        // 15 coalesced row gathers, all issued up front (MLP ~16)
        float v[16];
        #pragma unroll
        for (int r = 0; r < NSCORE; r++) {
            const int row = __shfl_sync(0xffffffffu, idx, r);
            const float4 w = *reinterpret_cast<const float4*>(
                out_emb + (size_t)row * DIM + lane * 4);
            v[r] = fmaf(t4.x, w.x, fmaf(t4.y, w.y, fmaf(t4.z, w.z, t4.w * w.w)));
        }
        v[15] = 0.0f;

        // Multi-value tree reduction: 16 lane-sums in 16 shuffles.
        // Step offset o: lanes with (lane & o) keep the upper half of their
        // registers, others keep the lower half; the discarded half is
        // exchanged with the XOR-o partner and accumulated.
        // After the loop + one o=1 finisher, lanes 2r and 2r+1 both hold the
        // full 32-lane sum of v[r]  (score index r = lane bits [4:1]).
        #pragma unroll
        for (int o = 16, nn = 8; o > 1; o >>= 1, nn >>= 1) {
            const bool up = (lane & o) != 0;
            #pragma unroll
            for (int i = 0; i < 8; i++) {
                if (i < nn) {
                    const float send  = up ? v[i] : v[i + nn];
                    const float keep  = up ? v[i + nn] : v[i];
                    const float other = __shfl_xor_sync(0xffffffffu, send, o);
                    v[i] = keep + other;
                }
            }
        }
        v[0] += __shfl_xor_sync(0xffffffffu, v[0], 1);
        const float myscore = v[0];

        // even lane 2r evaluates score r; odd lanes contribute zero
        float pv = 0.0f, nv = 0.0f;
        if ((lane & 1) == 0) {
            const int r = lane >> 1;
            if (r < C_MAX) {
                if (r < len) pv = neg_logsig(myscore);
            } else if (r < NSCORE) {
                nv = neg_logsig(-myscore);
            }
        }

        #pragma unroll
        for (int o = 16; o > 0; o >>= 1) {
            pv += __shfl_xor_sync(0xffffffffu, pv, o);
            nv += __shfl_xor_sync(0xffffffffu, nv, o);
        }

        if (len > 0) {
            pos_per = pv / (float)len;
            neg_per = nv * (1.0f / (float)K_NEG);
        }
    }

    if (lane == 0) {
        s_pos[wib] = pos_per;
        s_neg[wib] = neg_per;
    }
    __syncthreads();

    if (threadIdx.x == 0) {
        float ps = 0.0f, ns = 0.0f;
        #pragma unroll
        for (int w = 0; w < WARPS_PER_BLOCK; w++) { ps += s_pos[w]; ns += s_neg[w]; }
        const float invB = 1.0f / (float)B_SAMPLES;
        atomicAdd(&out[0], ps * invB);
        atomicAdd(&out[1], ns * invB);
    }
}

extern "C" void kernel_launch(void* const* d_in, const int* in_sizes, int n_in,
                              void* d_out, int out_size) {
    const int*   tw      = (const int*)d_in[0];
    const int*   cw      = (const int*)d_in[1];
    const int*   cl      = (const int*)d_in[2];
    const int*   nw      = (const int*)d_in[3];
    const float* in_emb  = (const float*)d_in[4];
    const float* out_emb = (const float*)d_in[5];
    float* out = (float*)d_out;

    zero_out_kernel<<<1, 32>>>(out);

    const int num_blocks = B_SAMPLES / WARPS_PER_BLOCK;
    skipgram_loss_kernel<<<num_blocks, THREADS>>>(tw, cw, cl, nw, in_emb, out_emb, out);
}

// round 3
// speedup vs baseline: 1.6122x; 1.0190x over previous
#include <cuda_runtime.h>
#include <cuda_bf16.h>
#include <cstdint>

// SkipGramMultiContext: B=16384, C_MAX=10, K_NEG=5, DIM=128, VOCAB=100000
// Output: float32[2] = {positive_loss, negative_loss}

#define B_SAMPLES 16384
#define C_MAX 10
#define K_NEG 5
#define DIM 128
#define NSCORE (C_MAX + K_NEG)   // 15
#define WARPS_PER_BLOCK 8
#define THREADS (WARPS_PER_BLOCK * 32)
#define NWARPS (B_SAMPLES / 2)   // 2 samples per warp

__device__ __forceinline__ float neg_logsig(float x) {
    // -log(sigmoid(x)) = -min(x,0) + log(1 + exp(-|x|)); log arg in (1,2]
    return __logf(1.0f + __expf(-fabsf(x))) - fminf(x, 0.0f);
}

__device__ __forceinline__ float dot4(float4 a, float4 b) {
    return fmaf(a.x, b.x, fmaf(a.y, b.y, fmaf(a.z, b.z, a.w * b.w)));
}

// Multi-value tree reduce of v[0..15] across 32 lanes.
// After this, lane l holds in v[0] the HALF-sum (over lanes with same bit0)
// of value index r = (l >> 1) & 15. Caller adds shfl_xor(v[0], 1) for full sum.
__device__ __forceinline__ void tree16(float v[16], int lane) {
    #pragma unroll
    for (int o = 16, nn = 8; o > 1; o >>= 1, nn >>= 1) {
        const bool up = (lane & o) != 0;
        #pragma unroll
        for (int i = 0; i < 8; i++) {
            if (i < nn) {
                const float send  = up ? v[i] : v[i + nn];
                const float keep  = up ? v[i + nn] : v[i];
                v[i] = keep + __shfl_xor_sync(0xffffffffu, send, o);
            }
        }
    }
}

__global__ void zero_out_kernel(float* out) {
    if (threadIdx.x < 2) out[threadIdx.x] = 0.0f;
}

__global__ __launch_bounds__(THREADS)
void skipgram_loss_kernel(const int* __restrict__ tw,
                          const int* __restrict__ cw,
                          const int* __restrict__ cl,
                          const int* __restrict__ nw,
                          const float* __restrict__ in_emb,
                          const float* __restrict__ out_emb,
                          float* __restrict__ out) {
    const int w    = (blockIdx.x * THREADS + threadIdx.x) >> 5;   // 0..NWARPS-1
    const int lane = threadIdx.x & 31;
    const int wib  = threadIdx.x >> 5;

    __shared__ float s_pos[WARPS_PER_BLOCK];
    __shared__ float s_neg[WARPS_PER_BLOCK];

    const int b0 = 2 * w;
    const int b1 = 2 * w + 1;

    // lanes 0..14 hold sample A's 15 indices, lanes 16..30 hold sample B's
    int idx = 0;
    {
        const int half = lane >> 4;            // 0 = A, 1 = B
        const int r    = lane & 15;
        const int b    = half ? b1 : b0;
        if (r < C_MAX)       idx = __ldg(&cw[b * C_MAX + r]);
        else if (r < NSCORE) idx = __ldg(&nw[b * K_NEG + (r - C_MAX)]);
    }
    const int lenA = __ldg(&cl[b0]);
    const int lenB = __ldg(&cl[b1]);

    // target row slices (coalesced LDG.128 per warp)
    const int tA = __ldg(&tw[b0]);
    const int tB = __ldg(&tw[b1]);
    const float4 t4A = *reinterpret_cast<const float4*>(in_emb + (size_t)tA * DIM + lane * 4);
    const float4 t4B = *reinterpret_cast<const float4*>(in_emb + (size_t)tB * DIM + lane * 4);

    // 30 coalesced row gathers, all front-batched (MLP ~32)
    float vA[16], vB[16];
    #pragma unroll
    for (int r = 0; r < NSCORE; r++) {
        const int rowA = __shfl_sync(0xffffffffu, idx, r);
        const int rowB = __shfl_sync(0xffffffffu, idx, 16 + r);
        const float4 ca = *reinterpret_cast<const float4*>(out_emb + (size_t)rowA * DIM + lane * 4);
        const float4 cb = *reinterpret_cast<const float4*>(out_emb + (size_t)rowB * DIM + lane * 4);
        vA[r] = dot4(t4A, ca);
        vB[r] = dot4(t4B, cb);
    }
    vA[15] = 0.0f;
    vB[15] = 0.0f;

    tree16(vA, lane);
    tree16(vB, lane);
    const float sA = vA[0] + __shfl_xor_sync(0xffffffffu, vA[0], 1);
    const float sB = vB[0] + __shfl_xor_sync(0xffffffffu, vB[0], 1);

    // even lane 2r evaluates A's score r; odd lane 2r+1 evaluates B's score r.
    // Contributions are pre-normalized so a single butterfly pair finishes both samples.
    const int  r   = (lane >> 1) & 15;
    const bool isB = (lane & 1) != 0;
    const float s  = isB ? sB : sA;
    const int  len = isB ? lenB : lenA;

    float pv = 0.0f, nv = 0.0f;
    if (r < C_MAX) {
        if (r < len) pv = neg_logsig(s) / (float)len;      // len >= 1 here
    } else if (r < NSCORE) {
        if (len > 0) nv = neg_logsig(-s) * (1.0f / (float)K_NEG);
    }

    #pragma unroll
    for (int o = 16; o > 0; o >>= 1) {
        pv += __shfl_xor_sync(0xffffffffu, pv, o);
        nv += __shfl_xor_sync(0xffffffffu, nv, o);
    }

    if (lane == 0) {
        s_pos[wib] = pv;    // sum over both samples, already per-sample normalized
        s_neg[wib] = nv;
    }
    __syncthreads();

    if (threadIdx.x == 0) {
        float ps = 0.0f, ns = 0.0f;
        #pragma unroll
        for (int ww = 0; ww < WARPS_PER_BLOCK; ww++) { ps += s_pos[ww]; ns += s_neg[ww]; }
        const float invB = 1.0f / (float)B_SAMPLES;
        atomicAdd(&out[0], ps * invB);
        atomicAdd(&out[1], ns * invB);
    }
}

extern "C" void kernel_launch(void* const* d_in, const int* in_sizes, int n_in,
                              void* d_out, int out_size) {
    const int*   tw      = (const int*)d_in[0];
    const int*   cw      = (const int*)d_in[1];
    const int*   cl      = (const int*)d_in[2];
    const int*   nw      = (const int*)d_in[3];
    const float* in_emb  = (const float*)d_in[4];
    const float* out_emb = (const float*)d_in[5];
    float* out = (float*)d_out;

    zero_out_kernel<<<1, 32>>>(out);

    const int num_blocks = NWARPS / WARPS_PER_BLOCK;   // 1024
    skipgram_loss_kernel<<<num_blocks, THREADS>>>(tw, cw, cl, nw, in_emb, out_emb, out);
}